// round 1
// baseline (speedup 1.0000x reference)
#include <cuda_runtime.h>
#include <math.h>

// Problem dims
#define NB 16     // batch
#define ND 1024   // DIM1 == DIM2
#define NL 512    // LATENT
#define NT 2048   // T

// ---------------------------------------------------------------------------
// Scratch (device globals; no runtime allocation allowed)
// ---------------------------------------------------------------------------
__device__ float g_TH[(size_t)NB * NL * NT];   // theta proj  [b, l, t]   64 MB
__device__ float g_PH[(size_t)NB * NL * NT];   // phi proj    [b, l, t]   64 MB
__device__ float g_GX[(size_t)NB * NL * NT];   // g proj      [b, l, t]   64 MB
__device__ float g_TX[(size_t)NB * NL * NT];   // t_x         [b, l, t]   64 MB
__device__ float g_S [(size_t)NB * NT * NT];   // scores / p  [b, t, s]  256 MB
__device__ float g_part[NB * 64 * 2];          // LN partial sums (deterministic)
__device__ float g_stats[NB * 2];              // per-batch mean, rstd

// ---------------------------------------------------------------------------
// Reduction helpers
// ---------------------------------------------------------------------------
__device__ __forceinline__ float warpMax(float v) {
    #pragma unroll
    for (int o = 16; o > 0; o >>= 1) v = fmaxf(v, __shfl_xor_sync(0xffffffffu, v, o));
    return v;
}
__device__ __forceinline__ float warpSum(float v) {
    #pragma unroll
    for (int o = 16; o > 0; o >>= 1) v += __shfl_xor_sync(0xffffffffu, v, o);
    return v;
}

// ---------------------------------------------------------------------------
// Projection GEMM:  C[b][m][n] = sum_k W[m][k] * X[b][k][n] + bias[m]
// W: [NL, ND] row-major.  X: [NB, ND, NT].  C: [NB, NL, NT].
// Tiles: BM=BN=128, BK=8, 256 threads, 8x8 micro-tile.
// ---------------------------------------------------------------------------
__global__ __launch_bounds__(256, 2) void k_proj(
    const float* __restrict__ W, const float* __restrict__ X,
    const float* __restrict__ bias, float* __restrict__ C)
{
    __shared__ float As[8][128];
    __shared__ float Bs[8][128];
    const int b  = blockIdx.z;
    const int m0 = blockIdx.y * 128;
    const int n0 = blockIdx.x * 128;
    const float* Xb = X + (size_t)b * ND * NT;
    float*       Cb = C + (size_t)b * NL * NT;
    const int tid = threadIdx.x;
    const int tx = tid & 15, ty = tid >> 4;
    const int ar = tid >> 1, ac = (tid & 1) * 4;       // A loader ([M,K] k-contig)
    const int bn = tid & 127, bk = (tid >> 7) * 4;     // B loader ([K,N] n-contig)

    float acc[8][8];
    #pragma unroll
    for (int i = 0; i < 8; i++)
        #pragma unroll
        for (int j = 0; j < 8; j++) acc[i][j] = 0.f;

    for (int k0 = 0; k0 < ND; k0 += 8) {
        float4 av = *(const float4*)(W + (size_t)(m0 + ar) * ND + k0 + ac);
        As[ac + 0][ar] = av.x; As[ac + 1][ar] = av.y;
        As[ac + 2][ar] = av.z; As[ac + 3][ar] = av.w;
        #pragma unroll
        for (int j = 0; j < 4; j++)
            Bs[bk + j][bn] = Xb[(size_t)(k0 + bk + j) * NT + n0 + bn];
        __syncthreads();
        #pragma unroll
        for (int k = 0; k < 8; k++) {
            float a[8], bv[8];
            #pragma unroll
            for (int i = 0; i < 8; i++) a[i] = As[k][ty * 8 + i];
            #pragma unroll
            for (int j = 0; j < 8; j++) bv[j] = Bs[k][tx * 8 + j];
            #pragma unroll
            for (int i = 0; i < 8; i++)
                #pragma unroll
                for (int j = 0; j < 8; j++)
                    acc[i][j] = fmaf(a[i], bv[j], acc[i][j]);
        }
        __syncthreads();
    }
    #pragma unroll
    for (int i = 0; i < 8; i++) {
        const int m = m0 + ty * 8 + i;
        const float bi = bias[m];
        #pragma unroll
        for (int j = 0; j < 8; j += 4) {
            float4 v = make_float4(acc[i][j] + bi, acc[i][j + 1] + bi,
                                   acc[i][j + 2] + bi, acc[i][j + 3] + bi);
            *(float4*)(Cb + (size_t)m * NT + n0 + tx * 8 + j) = v;
        }
    }
}

// ---------------------------------------------------------------------------
// Scores GEMM (TN): S[b][t][s] = sum_l TH[b][l][t] * PH[b][l][s]
// Both operands [K=NL, M/N=NT] with unit stride along m/n.
// ---------------------------------------------------------------------------
__global__ __launch_bounds__(256, 2) void k_scores(
    const float* __restrict__ TH, const float* __restrict__ PH,
    float* __restrict__ S)
{
    __shared__ float As[8][128];
    __shared__ float Bs[8][128];
    const int b  = blockIdx.z;
    const int m0 = blockIdx.y * 128;
    const int n0 = blockIdx.x * 128;
    const float* A  = TH + (size_t)b * NL * NT;
    const float* Bp = PH + (size_t)b * NL * NT;
    float*       Sb = S  + (size_t)b * NT * NT;
    const int tid = threadIdx.x;
    const int tx = tid & 15, ty = tid >> 4;
    const int lm = tid & 127, lk = (tid >> 7) * 4;

    float acc[8][8];
    #pragma unroll
    for (int i = 0; i < 8; i++)
        #pragma unroll
        for (int j = 0; j < 8; j++) acc[i][j] = 0.f;

    for (int k0 = 0; k0 < NL; k0 += 8) {
        #pragma unroll
        for (int j = 0; j < 4; j++) {
            const int kk = lk + j;
            As[kk][lm] = A [(size_t)(k0 + kk) * NT + m0 + lm];
            Bs[kk][lm] = Bp[(size_t)(k0 + kk) * NT + n0 + lm];
        }
        __syncthreads();
        #pragma unroll
        for (int k = 0; k < 8; k++) {
            float a[8], bv[8];
            #pragma unroll
            for (int i = 0; i < 8; i++) a[i] = As[k][ty * 8 + i];
            #pragma unroll
            for (int j = 0; j < 8; j++) bv[j] = Bs[k][tx * 8 + j];
            #pragma unroll
            for (int i = 0; i < 8; i++)
                #pragma unroll
                for (int j = 0; j < 8; j++)
                    acc[i][j] = fmaf(a[i], bv[j], acc[i][j]);
        }
        __syncthreads();
    }
    #pragma unroll
    for (int i = 0; i < 8; i++) {
        const int m = m0 + ty * 8 + i;
        #pragma unroll
        for (int j = 0; j < 8; j += 4) {
            float4 v = make_float4(acc[i][j], acc[i][j + 1], acc[i][j + 2], acc[i][j + 3]);
            *(float4*)(Sb + (size_t)m * NT + n0 + tx * 8 + j) = v;
        }
    }
}

// ---------------------------------------------------------------------------
// Row softmax in place on S: one block per (b, t) row of 2048 floats.
// ---------------------------------------------------------------------------
__global__ __launch_bounds__(256) void k_softmax(float* __restrict__ S)
{
    float* p = S + (size_t)blockIdx.x * NT;
    const int tid = threadIdx.x;
    float4 v0 = ((float4*)p)[tid];
    float4 v1 = ((float4*)p)[tid + 256];

    __shared__ float sm[8];
    float m = fmaxf(fmaxf(fmaxf(v0.x, v0.y), fmaxf(v0.z, v0.w)),
                    fmaxf(fmaxf(v1.x, v1.y), fmaxf(v1.z, v1.w)));
    m = warpMax(m);
    if ((tid & 31) == 0) sm[tid >> 5] = m;
    __syncthreads();
    if (tid < 32) {
        float t = (tid < 8) ? sm[tid] : -1e30f;
        t = warpMax(t);
        if (tid == 0) sm[0] = t;
    }
    __syncthreads();
    const float bm = sm[0];
    __syncthreads();

    v0.x = __expf(v0.x - bm); v0.y = __expf(v0.y - bm);
    v0.z = __expf(v0.z - bm); v0.w = __expf(v0.w - bm);
    v1.x = __expf(v1.x - bm); v1.y = __expf(v1.y - bm);
    v1.z = __expf(v1.z - bm); v1.w = __expf(v1.w - bm);
    float s = v0.x + v0.y + v0.z + v0.w + v1.x + v1.y + v1.z + v1.w;
    s = warpSum(s);
    if ((tid & 31) == 0) sm[tid >> 5] = s;
    __syncthreads();
    if (tid < 32) {
        float t = (tid < 8) ? sm[tid] : 0.f;
        t = warpSum(t);
        if (tid == 0) sm[0] = t;
    }
    __syncthreads();
    const float inv = 1.f / sm[0];
    v0.x *= inv; v0.y *= inv; v0.z *= inv; v0.w *= inv;
    v1.x *= inv; v1.y *= inv; v1.z *= inv; v1.w *= inv;
    ((float4*)p)[tid] = v0;
    ((float4*)p)[tid + 256] = v1;
}

// ---------------------------------------------------------------------------
// Attention-apply GEMM (NT): TX[b][l][t] = sum_s GX[b][l][s] * P[b][t][s]
// A = GX [M=NL, K=NT] k-contig, B = P [N=NT, K=NT] k-contig.
// ---------------------------------------------------------------------------
__global__ __launch_bounds__(256, 2) void k_tx(
    const float* __restrict__ GX, const float* __restrict__ P,
    float* __restrict__ TX)
{
    __shared__ float As[8][128];
    __shared__ float Bs[8][128];
    const int b  = blockIdx.z;
    const int m0 = blockIdx.y * 128;
    const int n0 = blockIdx.x * 128;
    const float* A  = GX + (size_t)b * NL * NT;
    const float* Bp = P  + (size_t)b * NT * NT;
    float*       Cb = TX + (size_t)b * NL * NT;
    const int tid = threadIdx.x;
    const int tx = tid & 15, ty = tid >> 4;
    const int ar = tid >> 1, ac = (tid & 1) * 4;
    const int bn = tid >> 1, bc = (tid & 1) * 4;

    float acc[8][8];
    #pragma unroll
    for (int i = 0; i < 8; i++)
        #pragma unroll
        for (int j = 0; j < 8; j++) acc[i][j] = 0.f;

    for (int k0 = 0; k0 < NT; k0 += 8) {
        float4 av = *(const float4*)(A + (size_t)(m0 + ar) * NT + k0 + ac);
        As[ac + 0][ar] = av.x; As[ac + 1][ar] = av.y;
        As[ac + 2][ar] = av.z; As[ac + 3][ar] = av.w;
        float4 bv4 = *(const float4*)(Bp + (size_t)(n0 + bn) * NT + k0 + bc);
        Bs[bc + 0][bn] = bv4.x; Bs[bc + 1][bn] = bv4.y;
        Bs[bc + 2][bn] = bv4.z; Bs[bc + 3][bn] = bv4.w;
        __syncthreads();
        #pragma unroll
        for (int k = 0; k < 8; k++) {
            float a[8], bv[8];
            #pragma unroll
            for (int i = 0; i < 8; i++) a[i] = As[k][ty * 8 + i];
            #pragma unroll
            for (int j = 0; j < 8; j++) bv[j] = Bs[k][tx * 8 + j];
            #pragma unroll
            for (int i = 0; i < 8; i++)
                #pragma unroll
                for (int j = 0; j < 8; j++)
                    acc[i][j] = fmaf(a[i], bv[j], acc[i][j]);
        }
        __syncthreads();
    }
    #pragma unroll
    for (int i = 0; i < 8; i++) {
        const int m = m0 + ty * 8 + i;
        #pragma unroll
        for (int j = 0; j < 8; j += 4) {
            float4 v = make_float4(acc[i][j], acc[i][j + 1], acc[i][j + 2], acc[i][j + 3]);
            *(float4*)(Cb + (size_t)m * NT + n0 + tx * 8 + j) = v;
        }
    }
}

// ---------------------------------------------------------------------------
// LayerNorm statistics: deterministic two-pass (partials -> fixed-order sum).
// ---------------------------------------------------------------------------
__global__ __launch_bounds__(256) void k_stats(const float* __restrict__ TX)
{
    const int b = blockIdx.x >> 6;
    const int chunk = blockIdx.x & 63;
    const int tid = threadIdx.x;
    const float4* p4 = (const float4*)(TX + (size_t)b * NL * NT
                                          + (size_t)chunk * (NL * NT / 64));
    float s = 0.f, q = 0.f;
    #pragma unroll 4
    for (int i = tid; i < 4096; i += 256) {
        float4 v = p4[i];
        s += v.x + v.y + v.z + v.w;
        q += v.x * v.x + v.y * v.y + v.z * v.z + v.w * v.w;
    }
    __shared__ float rs[8], rq[8];
    s = warpSum(s); q = warpSum(q);
    if ((tid & 31) == 0) { rs[tid >> 5] = s; rq[tid >> 5] = q; }
    __syncthreads();
    if (tid < 32) {
        float t  = (tid < 8) ? rs[tid] : 0.f;
        float t2 = (tid < 8) ? rq[tid] : 0.f;
        t = warpSum(t); t2 = warpSum(t2);
        if (tid == 0) {
            g_part[blockIdx.x * 2]     = t;
            g_part[blockIdx.x * 2 + 1] = t2;
        }
    }
}

__global__ void k_finalize()
{
    const int b = threadIdx.x;
    if (b >= NB) return;
    float s = 0.f, q = 0.f;
    for (int c = 0; c < 64; c++) {
        s += g_part[(b * 64 + c) * 2];
        q += g_part[(b * 64 + c) * 2 + 1];
    }
    const float n = (float)NL * (float)NT;
    const float mean = s / n;
    const float var  = q / n - mean * mean;
    g_stats[2 * b]     = mean;
    g_stats[2 * b + 1] = rsqrtf(var + 1e-5f);
}

// ---------------------------------------------------------------------------
// Output GEMM with fused LayerNorm+ReLU on the K-side tile and fused
// bias + residual epilogue:
//   Out[b][o][t] = sum_l OW[o][l]*relu((TX[b][l][t]-mu)*rstd*G[l][t]+Be[l][t])
//                  + ob[o] + in2[b][o][t]
// ---------------------------------------------------------------------------
__global__ __launch_bounds__(256, 2) void k_out(
    const float* __restrict__ OW, const float* __restrict__ TX,
    const float* __restrict__ G, const float* __restrict__ Be,
    const float* __restrict__ ob, const float* __restrict__ in2,
    float* __restrict__ Out)
{
    __shared__ float As[8][128];
    __shared__ float Bs[8][128];
    const int b  = blockIdx.z;
    const int m0 = blockIdx.y * 128;
    const int n0 = blockIdx.x * 128;
    const float mu   = g_stats[2 * b];
    const float rstd = g_stats[2 * b + 1];
    const float* TXb = TX + (size_t)b * NL * NT;
    const int tid = threadIdx.x;
    const int tx = tid & 15, ty = tid >> 4;
    const int ar = tid >> 1, ac = (tid & 1) * 4;       // OW [ND, NL] k-contig
    const int bn = tid & 127, bk = (tid >> 7) * 4;

    float acc[8][8];
    #pragma unroll
    for (int i = 0; i < 8; i++)
        #pragma unroll
        for (int j = 0; j < 8; j++) acc[i][j] = 0.f;

    for (int k0 = 0; k0 < NL; k0 += 8) {
        float4 av = *(const float4*)(OW + (size_t)(m0 + ar) * NL + k0 + ac);
        As[ac + 0][ar] = av.x; As[ac + 1][ar] = av.y;
        As[ac + 2][ar] = av.z; As[ac + 3][ar] = av.w;
        #pragma unroll
        for (int j = 0; j < 4; j++) {
            const int kk = k0 + bk + j;
            const size_t off = (size_t)kk * NT + n0 + bn;
            float h = (TXb[off] - mu) * rstd * G[off] + Be[off];
            Bs[bk + j][bn] = fmaxf(h, 0.f);
        }
        __syncthreads();
        #pragma unroll
        for (int k = 0; k < 8; k++) {
            float a[8], bv[8];
            #pragma unroll
            for (int i = 0; i < 8; i++) a[i] = As[k][ty * 8 + i];
            #pragma unroll
            for (int j = 0; j < 8; j++) bv[j] = Bs[k][tx * 8 + j];
            #pragma unroll
            for (int i = 0; i < 8; i++)
                #pragma unroll
                for (int j = 0; j < 8; j++)
                    acc[i][j] = fmaf(a[i], bv[j], acc[i][j]);
        }
        __syncthreads();
    }
    #pragma unroll
    for (int i = 0; i < 8; i++) {
        const int m = m0 + ty * 8 + i;
        const float obi = ob[m];
        const size_t base = ((size_t)b * ND + m) * NT + n0 + tx * 8;
        #pragma unroll
        for (int j = 0; j < 8; j += 4) {
            float4 r = *(const float4*)(in2 + base + j);
            float4 v = make_float4(acc[i][j]     + obi + r.x,
                                   acc[i][j + 1] + obi + r.y,
                                   acc[i][j + 2] + obi + r.z,
                                   acc[i][j + 3] + obi + r.w);
            *(float4*)(Out + base + j) = v;
        }
    }
}

// ---------------------------------------------------------------------------
// Launch
// ---------------------------------------------------------------------------
extern "C" void kernel_launch(void* const* d_in, const int* in_sizes, int n_in,
                              void* d_out, int out_size)
{
    const float* input1  = (const float*)d_in[0];
    const float* input2  = (const float*)d_in[1];
    const float* theta_w = (const float*)d_in[2];
    const float* theta_b = (const float*)d_in[3];
    const float* phi_w   = (const float*)d_in[4];
    const float* phi_b   = (const float*)d_in[5];
    const float* g_w     = (const float*)d_in[6];
    const float* g_b     = (const float*)d_in[7];
    const float* ln_g    = (const float*)d_in[8];
    const float* ln_b    = (const float*)d_in[9];
    const float* out_w   = (const float*)d_in[10];
    const float* out_b   = (const float*)d_in[11];
    float* out = (float*)d_out;

    float *TH, *PH, *GX, *TX, *S;
    cudaGetSymbolAddress((void**)&TH, g_TH);
    cudaGetSymbolAddress((void**)&PH, g_PH);
    cudaGetSymbolAddress((void**)&GX, g_GX);
    cudaGetSymbolAddress((void**)&TX, g_TX);
    cudaGetSymbolAddress((void**)&S,  g_S);

    dim3 blk(256);

    dim3 gproj(NT / 128, NL / 128, NB);
    k_proj<<<gproj, blk>>>(theta_w, input2, theta_b, TH);
    k_proj<<<gproj, blk>>>(phi_w,   input1, phi_b,   PH);
    k_proj<<<gproj, blk>>>(g_w,     input1, g_b,     GX);

    dim3 gsc(NT / 128, NT / 128, NB);
    k_scores<<<gsc, blk>>>(TH, PH, S);

    k_softmax<<<NB * NT, 256>>>(S);

    dim3 gtx(NT / 128, NL / 128, NB);
    k_tx<<<gtx, blk>>>(GX, S, TX);

    k_stats<<<NB * 64, 256>>>(TX);
    k_finalize<<<1, NB>>>();

    dim3 gout(NT / 128, ND / 128, NB);
    k_out<<<gout, blk>>>(out_w, TX, ln_g, ln_b, out_b, input2, out);
}

// round 3
// speedup vs baseline: 2.0008x; 2.0008x over previous
#include <cuda_runtime.h>
#include <math.h>
#include <stdint.h>

#define NB 16
#define ND 1024
#define NL 512
#define NT 2048

// ---------------------------------------------------------------------------
// Scratch
// ---------------------------------------------------------------------------
__device__ float g_TH[(size_t)NB * NT * NL];   // theta proj [b,t,l]
__device__ float g_PH[(size_t)NB * NT * NL];   // phi proj   [b,s,l]
__device__ float g_GX[(size_t)NB * NT * NL];   // g proj     [b,s,l]
__device__ float g_TX[(size_t)NB * NT * NL];   // t_x        [b,t,l]
__device__ float g_H [(size_t)NB * NT * NL];   // LN+ReLU    [b,t,l]
__device__ float g_S [(size_t)NB * NT * NT];   // scores/p   [b,t,s]
__device__ float g_G2[(size_t)NT * NL];        // gamma^T [t,l]
__device__ float g_B2[(size_t)NT * NL];        // beta^T  [t,l]
__device__ float g_part[NB * 64 * 2];
__device__ float g_stats[NB * 2];

// Stage buffer geometry: tile A + tile B per stage, 3 stages.
//  mode0 tile: 128 rows x 32 floats, rows padded to 36 floats (144 B)  = 18432 B
//  mode1 tile: 32 rows x 128 floats, rows padded to 132 floats (528 B) = 16896 B
static constexpr int TILE_A_OFF = 0;
static constexpr int TILE_B_OFF = 18432;
static constexpr int STAGE_BYTES = 36864;
static constexpr int SMEMB = 3 * STAGE_BYTES;   // 110592

// ---------------------------------------------------------------------------
// PTX helpers
// ---------------------------------------------------------------------------
__device__ __forceinline__ uint32_t f2tf(float f) {
    uint32_t r;
    asm("cvt.rna.tf32.f32 %0, %1;" : "=r"(r) : "f"(f));
    return r;
}

__device__ __forceinline__ void mma8(float* c, const uint32_t* a, const uint32_t* b) {
    asm volatile(
        "mma.sync.aligned.m16n8k8.row.col.f32.tf32.tf32.f32 "
        "{%0,%1,%2,%3}, {%4,%5,%6,%7}, {%8,%9}, {%0,%1,%2,%3};"
        : "+f"(c[0]), "+f"(c[1]), "+f"(c[2]), "+f"(c[3])
        : "r"(a[0]), "r"(a[1]), "r"(a[2]), "r"(a[3]), "r"(b[0]), "r"(b[1]));
}

__device__ __forceinline__ void cp16(uint32_t d, const float* s) {
    asm volatile("cp.async.cg.shared.global [%0], [%1], 16;" :: "r"(d), "l"(s));
}
__device__ __forceinline__ void cp_commit() {
    asm volatile("cp.async.commit_group;");
}
__device__ __forceinline__ void cp_wait2() {
    asm volatile("cp.async.wait_group 2;");
}

// Staging (256 threads, 16B chunks), natural gmem orientation.
// mode0: 128 rows x 32 floats -> smem rows padded to 144 B
__device__ __forceinline__ void stage_m0(uint32_t dst, const float* src, int stride) {
    const int tid = threadIdx.x;
    #pragma unroll
    for (int i = 0; i < 4; i++) {
        int id = tid + i * 256;
        int r = id >> 3, c = id & 7;
        cp16(dst + r * 144 + c * 16, src + (size_t)r * stride + c * 4);
    }
}
// mode1: 32 rows x 128 floats -> smem rows padded to 528 B
__device__ __forceinline__ void stage_m1(uint32_t dst, const float* src, int stride) {
    const int tid = threadIdx.x;
    #pragma unroll
    for (int i = 0; i < 4; i++) {
        int id = tid + i * 256;
        int r = id >> 5, c = id & 31;
        cp16(dst + r * 528 + c * 16, src + (size_t)r * stride + c * 4);
    }
}

// ---------------------------------------------------------------------------
// Pipelined GEMM core: 128x128 block, 8 warps (warp tile 32m x 64n),
// K chunks of 32. AM/BM select operand orientation; THREE = 3x-tf32.
//   A frag element (r,c):  AM0: sA[r*36+c]   AM1: sA[c*132+r]
//   B frag element (k,n):  BM0: sB[n*36+k]   BM1: sB[k*132+n]
// ---------------------------------------------------------------------------
template<int AM, int BM, bool THREE, class StageF>
__device__ __forceinline__ void gemm_run(int KC, StageF stage, float (*acc)[8][4])
{
    extern __shared__ char dsm[];
    const uint32_t sb = (uint32_t)__cvta_generic_to_shared(dsm);
    const int tid  = threadIdx.x;
    const int lane = tid & 31;
    const int m_off = ((tid >> 5) & 3) * 32;
    const int n_off = (tid >> 7) * 64;
    const int gid = lane >> 2, tig = lane & 3;

    #pragma unroll
    for (int i = 0; i < 2; i++)
        #pragma unroll
        for (int j = 0; j < 8; j++)
            #pragma unroll
            for (int k = 0; k < 4; k++) acc[i][j][k] = 0.f;

    #pragma unroll
    for (int p = 0; p < 3; p++) {
        if (p < KC) stage(p, sb + p * STAGE_BYTES, sb + p * STAGE_BYTES + TILE_B_OFF);
        cp_commit();
    }

    for (int kc = 0; kc < KC; kc++) {
        const int s = kc % 3;
        const float* sA = (const float*)(dsm + s * STAGE_BYTES);
        const float* sB = (const float*)(dsm + s * STAGE_BYTES + TILE_B_OFF);
        cp_wait2();
        __syncthreads();

        #pragma unroll
        for (int k8 = 0; k8 < 4; k8++) {
            const int kb = k8 * 8;
            // --- A fragments ---
            float av[2][4];
            #pragma unroll
            for (int mt = 0; mt < 2; mt++) {
                const int r0 = m_off + mt * 16 + gid;
                if (AM == 0) {
                    av[mt][0] = sA[r0 * 36 + kb + tig];
                    av[mt][1] = sA[(r0 + 8) * 36 + kb + tig];
                    av[mt][2] = sA[r0 * 36 + kb + tig + 4];
                    av[mt][3] = sA[(r0 + 8) * 36 + kb + tig + 4];
                } else {
                    av[mt][0] = sA[(kb + tig) * 132 + r0];
                    av[mt][1] = sA[(kb + tig) * 132 + r0 + 8];
                    av[mt][2] = sA[(kb + tig + 4) * 132 + r0];
                    av[mt][3] = sA[(kb + tig + 4) * 132 + r0 + 8];
                }
            }
            // --- B fragments ---
            float bv[8][2];
            #pragma unroll
            for (int nt = 0; nt < 8; nt++) {
                const int n = n_off + nt * 8 + gid;
                if (BM == 0) {
                    bv[nt][0] = sB[n * 36 + kb + tig];
                    bv[nt][1] = sB[n * 36 + kb + tig + 4];
                } else {
                    bv[nt][0] = sB[(kb + tig) * 132 + n];
                    bv[nt][1] = sB[(kb + tig + 4) * 132 + n];
                }
            }

            if (!THREE) {
                uint32_t a[2][4], bb[8][2];
                #pragma unroll
                for (int mt = 0; mt < 2; mt++)
                    #pragma unroll
                    for (int q = 0; q < 4; q++) a[mt][q] = f2tf(av[mt][q]);
                #pragma unroll
                for (int nt = 0; nt < 8; nt++) {
                    bb[nt][0] = f2tf(bv[nt][0]);
                    bb[nt][1] = f2tf(bv[nt][1]);
                }
                #pragma unroll
                for (int mt = 0; mt < 2; mt++)
                    #pragma unroll
                    for (int nt = 0; nt < 8; nt++)
                        mma8(acc[mt][nt], a[mt], bb[nt]);
            } else {
                uint32_t ah[2][4], al[2][4], bh[8][2], bl[8][2];
                #pragma unroll
                for (int mt = 0; mt < 2; mt++)
                    #pragma unroll
                    for (int q = 0; q < 4; q++) {
                        ah[mt][q] = f2tf(av[mt][q]);
                        al[mt][q] = f2tf(av[mt][q] - __uint_as_float(ah[mt][q]));
                    }
                #pragma unroll
                for (int nt = 0; nt < 8; nt++)
                    #pragma unroll
                    for (int q = 0; q < 2; q++) {
                        bh[nt][q] = f2tf(bv[nt][q]);
                        bl[nt][q] = f2tf(bv[nt][q] - __uint_as_float(bh[nt][q]));
                    }
                #pragma unroll
                for (int mt = 0; mt < 2; mt++)
                    #pragma unroll
                    for (int nt = 0; nt < 8; nt++) {
                        mma8(acc[mt][nt], al[mt], bh[nt]);
                        mma8(acc[mt][nt], ah[mt], bl[nt]);
                        mma8(acc[mt][nt], ah[mt], bh[nt]);
                    }
            }
        }
        __syncthreads();
        if (kc + 3 < KC)
            stage(kc + 3, sb + s * STAGE_BYTES, sb + s * STAGE_BYTES + TILE_B_OFF);
        cp_commit();
    }
}

// ---------------------------------------------------------------------------
// GEMM kernels
// ---------------------------------------------------------------------------

// Projection: C[b,t,l] = sum_d X[b,d,t] * W[l,d] + bias[l]
// A = X (M=t, mode1), B = W (N=l, mode0). Grid: (NL/128, NT/128, NB)
template<bool THREE>
__global__ __launch_bounds__(256)
void k_proj_tc(const float* __restrict__ W, const float* __restrict__ X,
               const float* __restrict__ bias, float* __restrict__ C)
{
    const int b  = blockIdx.z;
    const int n0 = blockIdx.x * 128;   // l
    const int m0 = blockIdx.y * 128;   // t
    const float* Xb = X + (size_t)b * ND * NT;

    float acc[2][8][4];
    auto stage = [&](int kc, uint32_t bA, uint32_t bB) {
        stage_m1(bA, Xb + (size_t)(kc * 32) * NT + m0, NT);
        stage_m0(bB, W  + (size_t)n0 * ND + kc * 32, ND);
    };
    gemm_run<1, 0, THREE>(ND / 32, stage, acc);

    const int tid = threadIdx.x, lane = tid & 31;
    const int m_off = ((tid >> 5) & 3) * 32, n_off = (tid >> 7) * 64;
    const int gid = lane >> 2, tig = lane & 3;
    float* Cb = C + (size_t)b * NT * NL;
    #pragma unroll
    for (int mt = 0; mt < 2; mt++) {
        const int r0 = m0 + m_off + mt * 16 + gid;
        #pragma unroll
        for (int nt = 0; nt < 8; nt++) {
            const int col = n0 + n_off + nt * 8 + tig * 2;
            float2 bi = *(const float2*)(bias + col);
            *(float2*)(Cb + (size_t)r0 * NL + col) =
                make_float2(acc[mt][nt][0] + bi.x, acc[mt][nt][1] + bi.y);
            *(float2*)(Cb + (size_t)(r0 + 8) * NL + col) =
                make_float2(acc[mt][nt][2] + bi.x, acc[mt][nt][3] + bi.y);
        }
    }
}

// Scores: S[b,t,s] = sum_l TH[b,t,l] * PH[b,s,l]. A/B mode0. Grid (16,16,NB)
__global__ __launch_bounds__(256)
void k_scores_tc(const float* __restrict__ TH, const float* __restrict__ PH,
                 float* __restrict__ S)
{
    const int b  = blockIdx.z;
    const int n0 = blockIdx.x * 128;   // s
    const int m0 = blockIdx.y * 128;   // t
    const float* A  = TH + (size_t)b * NT * NL;
    const float* Bp = PH + (size_t)b * NT * NL;

    float acc[2][8][4];
    auto stage = [&](int kc, uint32_t bA, uint32_t bB) {
        stage_m0(bA, A  + (size_t)m0 * NL + kc * 32, NL);
        stage_m0(bB, Bp + (size_t)n0 * NL + kc * 32, NL);
    };
    gemm_run<0, 0, true>(NL / 32, stage, acc);

    const int tid = threadIdx.x, lane = tid & 31;
    const int m_off = ((tid >> 5) & 3) * 32, n_off = (tid >> 7) * 64;
    const int gid = lane >> 2, tig = lane & 3;
    float* Sb = S + (size_t)b * NT * NT;
    #pragma unroll
    for (int mt = 0; mt < 2; mt++) {
        const int r0 = m0 + m_off + mt * 16 + gid;
        #pragma unroll
        for (int nt = 0; nt < 8; nt++) {
            const int col = n0 + n_off + nt * 8 + tig * 2;
            *(float2*)(Sb + (size_t)r0 * NT + col) =
                make_float2(acc[mt][nt][0], acc[mt][nt][1]);
            *(float2*)(Sb + (size_t)(r0 + 8) * NT + col) =
                make_float2(acc[mt][nt][2], acc[mt][nt][3]);
        }
    }
}

// t_x: TX[b,t,l] = sum_s P[b,t,s] * GX[b,s,l]. A=P mode0, B=GX mode1.
// Grid (NL/128, NT/128, NB)
__global__ __launch_bounds__(256)
void k_tx_tc(const float* __restrict__ P, const float* __restrict__ GX,
             float* __restrict__ TX)
{
    const int b  = blockIdx.z;
    const int n0 = blockIdx.x * 128;   // l
    const int m0 = blockIdx.y * 128;   // t
    const float* A  = P  + (size_t)b * NT * NT;
    const float* Bp = GX + (size_t)b * NT * NL;

    float acc[2][8][4];
    auto stage = [&](int kc, uint32_t bA, uint32_t bB) {
        stage_m0(bA, A  + (size_t)m0 * NT + kc * 32, NT);
        stage_m1(bB, Bp + (size_t)(kc * 32) * NL + n0, NL);
    };
    gemm_run<0, 1, false>(NT / 32, stage, acc);

    const int tid = threadIdx.x, lane = tid & 31;
    const int m_off = ((tid >> 5) & 3) * 32, n_off = (tid >> 7) * 64;
    const int gid = lane >> 2, tig = lane & 3;
    float* Tb = TX + (size_t)b * NT * NL;
    #pragma unroll
    for (int mt = 0; mt < 2; mt++) {
        const int r0 = m0 + m_off + mt * 16 + gid;
        #pragma unroll
        for (int nt = 0; nt < 8; nt++) {
            const int col = n0 + n_off + nt * 8 + tig * 2;
            *(float2*)(Tb + (size_t)r0 * NL + col) =
                make_float2(acc[mt][nt][0], acc[mt][nt][1]);
            *(float2*)(Tb + (size_t)(r0 + 8) * NL + col) =
                make_float2(acc[mt][nt][2], acc[mt][nt][3]);
        }
    }
}

// Out: Out[b,o,t] = sum_l OW[o,l] * H[b,t,l] + ob[o] + in2[b,o,t]
// A=OW mode0 (M=o), B=H mode0 (N=t). Grid (NT/128, ND/128, NB)
__global__ __launch_bounds__(256)
void k_out_tc(const float* __restrict__ OW, const float* __restrict__ H,
              const float* __restrict__ ob, const float* __restrict__ in2,
              float* __restrict__ Out)
{
    const int b  = blockIdx.z;
    const int n0 = blockIdx.x * 128;   // t
    const int m0 = blockIdx.y * 128;   // o
    const float* Hb = H + (size_t)b * NT * NL;

    float acc[2][8][4];
    auto stage = [&](int kc, uint32_t bA, uint32_t bB) {
        stage_m0(bA, OW + (size_t)m0 * NL + kc * 32, NL);
        stage_m0(bB, Hb + (size_t)n0 * NL + kc * 32, NL);
    };
    gemm_run<0, 0, false>(NL / 32, stage, acc);

    const int tid = threadIdx.x, lane = tid & 31;
    const int m_off = ((tid >> 5) & 3) * 32, n_off = (tid >> 7) * 64;
    const int gid = lane >> 2, tig = lane & 3;
    #pragma unroll
    for (int mt = 0; mt < 2; mt++) {
        const int r0 = m0 + m_off + mt * 16 + gid;
        const float bi0 = ob[r0], bi1 = ob[r0 + 8];
        const size_t base0 = ((size_t)b * ND + r0) * NT;
        const size_t base1 = ((size_t)b * ND + r0 + 8) * NT;
        #pragma unroll
        for (int nt = 0; nt < 8; nt++) {
            const int col = n0 + n_off + nt * 8 + tig * 2;
            float2 q0 = *(const float2*)(in2 + base0 + col);
            float2 q1 = *(const float2*)(in2 + base1 + col);
            *(float2*)(Out + base0 + col) =
                make_float2(acc[mt][nt][0] + bi0 + q0.x, acc[mt][nt][1] + bi0 + q0.y);
            *(float2*)(Out + base1 + col) =
                make_float2(acc[mt][nt][2] + bi1 + q1.x, acc[mt][nt][3] + bi1 + q1.y);
        }
    }
}

// ---------------------------------------------------------------------------
// Elementwise / reductions
// ---------------------------------------------------------------------------
__device__ __forceinline__ float warpMax(float v) {
    #pragma unroll
    for (int o = 16; o > 0; o >>= 1) v = fmaxf(v, __shfl_xor_sync(0xffffffffu, v, o));
    return v;
}
__device__ __forceinline__ float warpSum(float v) {
    #pragma unroll
    for (int o = 16; o > 0; o >>= 1) v += __shfl_xor_sync(0xffffffffu, v, o);
    return v;
}

__global__ __launch_bounds__(256) void k_softmax(float* __restrict__ S)
{
    float* p = S + (size_t)blockIdx.x * NT;
    const int tid = threadIdx.x;
    float4 v0 = ((float4*)p)[tid];
    float4 v1 = ((float4*)p)[tid + 256];

    __shared__ float sm[8];
    float m = fmaxf(fmaxf(fmaxf(v0.x, v0.y), fmaxf(v0.z, v0.w)),
                    fmaxf(fmaxf(v1.x, v1.y), fmaxf(v1.z, v1.w)));
    m = warpMax(m);
    if ((tid & 31) == 0) sm[tid >> 5] = m;
    __syncthreads();
    if (tid < 32) {
        float t = (tid < 8) ? sm[tid] : -1e30f;
        t = warpMax(t);
        if (tid == 0) sm[0] = t;
    }
    __syncthreads();
    const float bm = sm[0];
    __syncthreads();

    v0.x = __expf(v0.x - bm); v0.y = __expf(v0.y - bm);
    v0.z = __expf(v0.z - bm); v0.w = __expf(v0.w - bm);
    v1.x = __expf(v1.x - bm); v1.y = __expf(v1.y - bm);
    v1.z = __expf(v1.z - bm); v1.w = __expf(v1.w - bm);
    float s = v0.x + v0.y + v0.z + v0.w + v1.x + v1.y + v1.z + v1.w;
    s = warpSum(s);
    if ((tid & 31) == 0) sm[tid >> 5] = s;
    __syncthreads();
    if (tid < 32) {
        float t = (tid < 8) ? sm[tid] : 0.f;
        t = warpSum(t);
        if (tid == 0) sm[0] = t;
    }
    __syncthreads();
    const float inv = 1.f / sm[0];
    v0.x *= inv; v0.y *= inv; v0.z *= inv; v0.w *= inv;
    v1.x *= inv; v1.y *= inv; v1.z *= inv; v1.w *= inv;
    ((float4*)p)[tid] = v0;
    ((float4*)p)[tid + 256] = v1;
}

__global__ __launch_bounds__(256) void k_stats(const float* __restrict__ TX)
{
    const int b = blockIdx.x >> 6;
    const int chunk = blockIdx.x & 63;
    const int tid = threadIdx.x;
    const float4* p4 = (const float4*)(TX + (size_t)b * NL * NT
                                          + (size_t)chunk * (NL * NT / 64));
    float s = 0.f, q = 0.f;
    #pragma unroll 4
    for (int i = tid; i < 4096; i += 256) {
        float4 v = p4[i];
        s += v.x + v.y + v.z + v.w;
        q += v.x * v.x + v.y * v.y + v.z * v.z + v.w * v.w;
    }
    __shared__ float rs[8], rq[8];
    s = warpSum(s); q = warpSum(q);
    if ((tid & 31) == 0) { rs[tid >> 5] = s; rq[tid >> 5] = q; }
    __syncthreads();
    if (tid < 32) {
        float t  = (tid < 8) ? rs[tid] : 0.f;
        float t2 = (tid < 8) ? rq[tid] : 0.f;
        t = warpSum(t); t2 = warpSum(t2);
        if (tid == 0) {
            g_part[blockIdx.x * 2]     = t;
            g_part[blockIdx.x * 2 + 1] = t2;
        }
    }
}

__global__ void k_finalize()
{
    const int b = threadIdx.x;
    if (b >= NB) return;
    float s = 0.f, q = 0.f;
    for (int c = 0; c < 64; c++) {
        s += g_part[(b * 64 + c) * 2];
        q += g_part[(b * 64 + c) * 2 + 1];
    }
    const float n = (float)NL * (float)NT;
    const float mean = s / n;
    const float var  = q / n - mean * mean;
    g_stats[2 * b]     = mean;
    g_stats[2 * b + 1] = rsqrtf(var + 1e-5f);
}

// gamma/beta transpose: src [NL, NT] -> dst [NT, NL]
__global__ void k_transpose(const float* __restrict__ src, float* __restrict__ dst)
{
    __shared__ float tile[32][33];
    const int x  = blockIdx.x * 32 + threadIdx.x;   // NT index
    const int y0 = blockIdx.y * 32;
    #pragma unroll
    for (int j = threadIdx.y; j < 32; j += 8)
        tile[j][threadIdx.x] = src[(size_t)(y0 + j) * NT + x];
    __syncthreads();
    const int xo  = blockIdx.y * 32 + threadIdx.x;  // NL index
    const int yo0 = blockIdx.x * 32;
    #pragma unroll
    for (int j = threadIdx.y; j < 32; j += 8)
        dst[(size_t)(yo0 + j) * NL + xo] = tile[threadIdx.x][j];
}

// H = relu((TX - mu) * rstd * G2 + B2), all [b,t,l]
__global__ __launch_bounds__(256) void k_ln(const float* __restrict__ TX,
                                            const float* __restrict__ G2,
                                            const float* __restrict__ B2,
                                            float* __restrict__ H)
{
    const int b = blockIdx.y;
    const size_t i = (size_t)blockIdx.x * 256 + threadIdx.x;
    const float mu = g_stats[2 * b], rs = g_stats[2 * b + 1];
    float4 x  = ((const float4*)(TX + (size_t)b * NL * NT))[i];
    float4 g  = ((const float4*)G2)[i];
    float4 be = ((const float4*)B2)[i];
    float4 h;
    h.x = fmaxf((x.x - mu) * rs * g.x + be.x, 0.f);
    h.y = fmaxf((x.y - mu) * rs * g.y + be.y, 0.f);
    h.z = fmaxf((x.z - mu) * rs * g.z + be.z, 0.f);
    h.w = fmaxf((x.w - mu) * rs * g.w + be.w, 0.f);
    ((float4*)(H + (size_t)b * NL * NT))[i] = h;
}

// ---------------------------------------------------------------------------
// Launch
// ---------------------------------------------------------------------------
extern "C" void kernel_launch(void* const* d_in, const int* in_sizes, int n_in,
                              void* d_out, int out_size)
{
    const float* input1  = (const float*)d_in[0];
    const float* input2  = (const float*)d_in[1];
    const float* theta_w = (const float*)d_in[2];
    const float* theta_b = (const float*)d_in[3];
    const float* phi_w   = (const float*)d_in[4];
    const float* phi_b   = (const float*)d_in[5];
    const float* g_w     = (const float*)d_in[6];
    const float* g_b     = (const float*)d_in[7];
    const float* ln_g    = (const float*)d_in[8];
    const float* ln_b    = (const float*)d_in[9];
    const float* out_w   = (const float*)d_in[10];
    const float* out_b   = (const float*)d_in[11];
    float* out = (float*)d_out;

    float *TH, *PH, *GX, *TX, *H, *S, *G2, *B2;
    cudaGetSymbolAddress((void**)&TH, g_TH);
    cudaGetSymbolAddress((void**)&PH, g_PH);
    cudaGetSymbolAddress((void**)&GX, g_GX);
    cudaGetSymbolAddress((void**)&TX, g_TX);
    cudaGetSymbolAddress((void**)&H,  g_H);
    cudaGetSymbolAddress((void**)&S,  g_S);
    cudaGetSymbolAddress((void**)&G2, g_G2);
    cudaGetSymbolAddress((void**)&B2, g_B2);

    cudaFuncSetAttribute(k_proj_tc<true>,  cudaFuncAttributeMaxDynamicSharedMemorySize, SMEMB);
    cudaFuncSetAttribute(k_proj_tc<false>, cudaFuncAttributeMaxDynamicSharedMemorySize, SMEMB);
    cudaFuncSetAttribute(k_scores_tc, cudaFuncAttributeMaxDynamicSharedMemorySize, SMEMB);
    cudaFuncSetAttribute(k_tx_tc,     cudaFuncAttributeMaxDynamicSharedMemorySize, SMEMB);
    cudaFuncSetAttribute(k_out_tc,    cudaFuncAttributeMaxDynamicSharedMemorySize, SMEMB);

    dim3 blk(256);

    dim3 gtr(NT / 32, NL / 32);
    k_transpose<<<gtr, dim3(32, 8)>>>(ln_g, G2);
    k_transpose<<<gtr, dim3(32, 8)>>>(ln_b, B2);

    dim3 gproj(NL / 128, NT / 128, NB);
    k_proj_tc<true ><<<gproj, blk, SMEMB>>>(theta_w, input2, theta_b, TH);
    k_proj_tc<true ><<<gproj, blk, SMEMB>>>(phi_w,   input1, phi_b,   PH);
    k_proj_tc<false><<<gproj, blk, SMEMB>>>(g_w,     input1, g_b,     GX);

    dim3 gsc(NT / 128, NT / 128, NB);
    k_scores_tc<<<gsc, blk, SMEMB>>>(TH, PH, S);

    k_softmax<<<NB * NT, 256>>>(S);

    dim3 gtx(NL / 128, NT / 128, NB);
    k_tx_tc<<<gtx, blk, SMEMB>>>(S, GX, TX);

    k_stats<<<NB * 64, 256>>>(TX);
    k_finalize<<<1, NB>>>();

    k_ln<<<dim3(NL * NT / 1024, NB), 256>>>(TX, G2, B2, H);

    dim3 gout(NT / 128, ND / 128, NB);
    k_out_tc<<<gout, blk, SMEMB>>>(out_w, H, out_b, input2, out);
}

// round 5
// speedup vs baseline: 2.1294x; 1.0643x over previous
#include <cuda_runtime.h>
#include <math.h>
#include <stdint.h>

#define NB 16
#define ND 1024
#define NL 512
#define NT 2048

// ---------------------------------------------------------------------------
// Scratch
// ---------------------------------------------------------------------------
__device__ float g_TH[(size_t)NB * NT * NL];   // theta proj [b,t,l]
__device__ float g_PH[(size_t)NB * NT * NL];   // phi proj   [b,s,l]
__device__ float g_GX[(size_t)NB * NT * NL];   // g proj     [b,s,l]
__device__ float g_TX[(size_t)NB * NT * NL];   // t_x        [b,t,l]
__device__ float g_H [(size_t)NB * NT * NL];   // LN+ReLU    [b,t,l]
__device__ float g_S [(size_t)NB * NT * NT];   // scores/p   [b,t,s]
__device__ float g_G2[(size_t)NT * NL];        // gamma^T [t,l]
__device__ float g_B2[(size_t)NT * NL];        // beta^T  [t,l]
__device__ float g_part[NB * 64 * 2];
__device__ float g_stats[NB * 2];

// Stage buffer geometry: tile A + tile B per stage, 3 stages.
static constexpr int TILE_B_OFF = 18432;
static constexpr int STAGE_BYTES = 36864;
static constexpr int SMEMB = 3 * STAGE_BYTES;   // 110592

// ---------------------------------------------------------------------------
// PTX helpers
// ---------------------------------------------------------------------------
__device__ __forceinline__ uint32_t f2tf(float f) {
    uint32_t r;
    asm("cvt.rna.tf32.f32 %0, %1;" : "=r"(r) : "f"(f));
    return r;
}

__device__ __forceinline__ void mma8(float* c, const uint32_t* a, const uint32_t* b) {
    asm volatile(
        "mma.sync.aligned.m16n8k8.row.col.f32.tf32.tf32.f32 "
        "{%0,%1,%2,%3}, {%4,%5,%6,%7}, {%8,%9}, {%0,%1,%2,%3};"
        : "+f"(c[0]), "+f"(c[1]), "+f"(c[2]), "+f"(c[3])
        : "r"(a[0]), "r"(a[1]), "r"(a[2]), "r"(a[3]), "r"(b[0]), "r"(b[1]));
}

__device__ __forceinline__ void cp16(uint32_t d, const float* s) {
    asm volatile("cp.async.cg.shared.global [%0], [%1], 16;" :: "r"(d), "l"(s));
}
__device__ __forceinline__ void cp_commit() {
    asm volatile("cp.async.commit_group;");
}
__device__ __forceinline__ void cp_wait2() {
    asm volatile("cp.async.wait_group 2;");
}

// Staging (256 threads, 16B chunks), natural gmem orientation.
// mode0: 128 rows x 32 floats -> smem rows padded to 144 B
__device__ __forceinline__ void stage_m0(uint32_t dst, const float* src, int stride) {
    const int tid = threadIdx.x;
    #pragma unroll
    for (int i = 0; i < 4; i++) {
        int id = tid + i * 256;
        int r = id >> 3, c = id & 7;
        cp16(dst + r * 144 + c * 16, src + (size_t)r * stride + c * 4);
    }
}
// mode1: 32 rows x 128 floats -> smem rows padded to 528 B
__device__ __forceinline__ void stage_m1(uint32_t dst, const float* src, int stride) {
    const int tid = threadIdx.x;
    #pragma unroll
    for (int i = 0; i < 4; i++) {
        int id = tid + i * 256;
        int r = id >> 5, c = id & 31;
        cp16(dst + r * 528 + c * 16, src + (size_t)r * stride + c * 4);
    }
}

// ---------------------------------------------------------------------------
// Pipelined GEMM core: 128x128 block, 8 warps (warp tile 32m x 64n),
// K chunks of 32. AM/BM select operand orientation; THREE = 3x-tf32.
//   A frag element (r,c):  AM0: sA[r*36+c]   AM1: sA[c*132+r]
//   B frag element (k,n):  BM0: sB[n*36+k]   BM1: sB[k*132+n]
// ---------------------------------------------------------------------------
template<int AM, int BM, bool THREE, class StageF>
__device__ __forceinline__ void gemm_run(int KC, StageF stage, float (*acc)[8][4])
{
    extern __shared__ char dsm[];
    const uint32_t sb = (uint32_t)__cvta_generic_to_shared(dsm);
    const int tid  = threadIdx.x;
    const int lane = tid & 31;
    const int m_off = ((tid >> 5) & 3) * 32;
    const int n_off = (tid >> 7) * 64;
    const int gid = lane >> 2, tig = lane & 3;

    #pragma unroll
    for (int i = 0; i < 2; i++)
        #pragma unroll
        for (int j = 0; j < 8; j++)
            #pragma unroll
            for (int k = 0; k < 4; k++) acc[i][j][k] = 0.f;

    #pragma unroll
    for (int p = 0; p < 3; p++) {
        if (p < KC) stage(p, sb + p * STAGE_BYTES, sb + p * STAGE_BYTES + TILE_B_OFF);
        cp_commit();
    }

    for (int kc = 0; kc < KC; kc++) {
        const int s = kc % 3;
        const float* sA = (const float*)(dsm + s * STAGE_BYTES);
        const float* sB = (const float*)(dsm + s * STAGE_BYTES + TILE_B_OFF);
        cp_wait2();
        __syncthreads();

        #pragma unroll
        for (int k8 = 0; k8 < 4; k8++) {
            const int kb = k8 * 8;
            // --- A fragments (floats) ---
            float av[2][4];
            #pragma unroll
            for (int mt = 0; mt < 2; mt++) {
                const int r0 = m_off + mt * 16 + gid;
                if (AM == 0) {
                    av[mt][0] = sA[r0 * 36 + kb + tig];
                    av[mt][1] = sA[(r0 + 8) * 36 + kb + tig];
                    av[mt][2] = sA[r0 * 36 + kb + tig + 4];
                    av[mt][3] = sA[(r0 + 8) * 36 + kb + tig + 4];
                } else {
                    av[mt][0] = sA[(kb + tig) * 132 + r0];
                    av[mt][1] = sA[(kb + tig) * 132 + r0 + 8];
                    av[mt][2] = sA[(kb + tig + 4) * 132 + r0];
                    av[mt][3] = sA[(kb + tig + 4) * 132 + r0 + 8];
                }
            }

            if (!THREE) {
                uint32_t a[2][4];
                #pragma unroll
                for (int mt = 0; mt < 2; mt++)
                    #pragma unroll
                    for (int q = 0; q < 4; q++) a[mt][q] = f2tf(av[mt][q]);
                #pragma unroll
                for (int nt = 0; nt < 8; nt++) {
                    const int n = n_off + nt * 8 + gid;
                    uint32_t bb[2];
                    if (BM == 0) {
                        bb[0] = f2tf(sB[n * 36 + kb + tig]);
                        bb[1] = f2tf(sB[n * 36 + kb + tig + 4]);
                    } else {
                        bb[0] = f2tf(sB[(kb + tig) * 132 + n]);
                        bb[1] = f2tf(sB[(kb + tig + 4) * 132 + n]);
                    }
                    #pragma unroll
                    for (int mt = 0; mt < 2; mt++)
                        mma8(acc[mt][nt], a[mt], bb);
                }
            } else {
                // 3x tf32: hi/lo split of both operands, 3 mmas per pair.
                uint32_t ah[2][4], al[2][4];
                #pragma unroll
                for (int mt = 0; mt < 2; mt++)
                    #pragma unroll
                    for (int q = 0; q < 4; q++) {
                        ah[mt][q] = f2tf(av[mt][q]);
                        al[mt][q] = f2tf(av[mt][q] - __uint_as_float(ah[mt][q]));
                    }
                // Convert B per-nt to keep the live register set small.
                #pragma unroll
                for (int nt = 0; nt < 8; nt++) {
                    const int n = n_off + nt * 8 + gid;
                    float b0, b1;
                    if (BM == 0) {
                        b0 = sB[n * 36 + kb + tig];
                        b1 = sB[n * 36 + kb + tig + 4];
                    } else {
                        b0 = sB[(kb + tig) * 132 + n];
                        b1 = sB[(kb + tig + 4) * 132 + n];
                    }
                    uint32_t bh[2], bl[2];
                    bh[0] = f2tf(b0); bl[0] = f2tf(b0 - __uint_as_float(bh[0]));
                    bh[1] = f2tf(b1); bl[1] = f2tf(b1 - __uint_as_float(bh[1]));
                    #pragma unroll
                    for (int mt = 0; mt < 2; mt++) {
                        mma8(acc[mt][nt], al[mt], bh);
                        mma8(acc[mt][nt], ah[mt], bl);
                        mma8(acc[mt][nt], ah[mt], bh);
                    }
                }
            }
        }
        __syncthreads();
        if (kc + 3 < KC)
            stage(kc + 3, sb + s * STAGE_BYTES, sb + s * STAGE_BYTES + TILE_B_OFF);
        cp_commit();
    }
}

// ---------------------------------------------------------------------------
// GEMM kernels
// ---------------------------------------------------------------------------

// Projection: C[b,t,l] = sum_d X[b,d,t] * W[l,d] + bias[l]
// A = X (M=t, mode1), B = W (N=l, mode0). Grid: (NL/128, NT/128, NB)
template<bool THREE>
__global__ __launch_bounds__(256, 2)
void k_proj_tc(const float* __restrict__ W, const float* __restrict__ X,
               const float* __restrict__ bias, float* __restrict__ C)
{
    const int b  = blockIdx.z;
    const int n0 = blockIdx.x * 128;   // l
    const int m0 = blockIdx.y * 128;   // t
    const float* Xb = X + (size_t)b * ND * NT;

    float acc[2][8][4];
    auto stage = [&](int kc, uint32_t bA, uint32_t bB) {
        stage_m1(bA, Xb + (size_t)(kc * 32) * NT + m0, NT);
        stage_m0(bB, W  + (size_t)n0 * ND + kc * 32, ND);
    };
    gemm_run<1, 0, THREE>(ND / 32, stage, acc);

    const int tid = threadIdx.x, lane = tid & 31;
    const int m_off = ((tid >> 5) & 3) * 32, n_off = (tid >> 7) * 64;
    const int gid = lane >> 2, tig = lane & 3;
    float* Cb = C + (size_t)b * NT * NL;
    #pragma unroll
    for (int mt = 0; mt < 2; mt++) {
        const int r0 = m0 + m_off + mt * 16 + gid;
        #pragma unroll
        for (int nt = 0; nt < 8; nt++) {
            const int col = n0 + n_off + nt * 8 + tig * 2;
            float2 bi = *(const float2*)(bias + col);
            *(float2*)(Cb + (size_t)r0 * NL + col) =
                make_float2(acc[mt][nt][0] + bi.x, acc[mt][nt][1] + bi.y);
            *(float2*)(Cb + (size_t)(r0 + 8) * NL + col) =
                make_float2(acc[mt][nt][2] + bi.x, acc[mt][nt][3] + bi.y);
        }
    }
}

// Scores: S[b,t,s] = sum_l TH[b,t,l] * PH[b,s,l]. A/B mode0. 3x. Grid (16,16,NB)
__global__ __launch_bounds__(256, 2)
void k_scores_tc(const float* __restrict__ TH, const float* __restrict__ PH,
                 float* __restrict__ S)
{
    const int b  = blockIdx.z;
    const int n0 = blockIdx.x * 128;   // s
    const int m0 = blockIdx.y * 128;   // t
    const float* A  = TH + (size_t)b * NT * NL;
    const float* Bp = PH + (size_t)b * NT * NL;

    float acc[2][8][4];
    auto stage = [&](int kc, uint32_t bA, uint32_t bB) {
        stage_m0(bA, A  + (size_t)m0 * NL + kc * 32, NL);
        stage_m0(bB, Bp + (size_t)n0 * NL + kc * 32, NL);
    };
    gemm_run<0, 0, true>(NL / 32, stage, acc);

    const int tid = threadIdx.x, lane = tid & 31;
    const int m_off = ((tid >> 5) & 3) * 32, n_off = (tid >> 7) * 64;
    const int gid = lane >> 2, tig = lane & 3;
    float* Sb = S + (size_t)b * NT * NT;
    #pragma unroll
    for (int mt = 0; mt < 2; mt++) {
        const int r0 = m0 + m_off + mt * 16 + gid;
        #pragma unroll
        for (int nt = 0; nt < 8; nt++) {
            const int col = n0 + n_off + nt * 8 + tig * 2;
            *(float2*)(Sb + (size_t)r0 * NT + col) =
                make_float2(acc[mt][nt][0], acc[mt][nt][1]);
            *(float2*)(Sb + (size_t)(r0 + 8) * NT + col) =
                make_float2(acc[mt][nt][2], acc[mt][nt][3]);
        }
    }
}

// t_x: TX[b,t,l] = sum_s P[b,t,s] * GX[b,s,l]. A=P mode0, B=GX mode1. 1x.
// Grid (NL/128, NT/128, NB)
__global__ __launch_bounds__(256, 2)
void k_tx_tc(const float* __restrict__ P, const float* __restrict__ GX,
             float* __restrict__ TX)
{
    const int b  = blockIdx.z;
    const int n0 = blockIdx.x * 128;   // l
    const int m0 = blockIdx.y * 128;   // t
    const float* A  = P  + (size_t)b * NT * NT;
    const float* Bp = GX + (size_t)b * NT * NL;

    float acc[2][8][4];
    auto stage = [&](int kc, uint32_t bA, uint32_t bB) {
        stage_m0(bA, A  + (size_t)m0 * NT + kc * 32, NT);
        stage_m1(bB, Bp + (size_t)(kc * 32) * NL + n0, NL);
    };
    gemm_run<0, 1, false>(NT / 32, stage, acc);

    const int tid = threadIdx.x, lane = tid & 31;
    const int m_off = ((tid >> 5) & 3) * 32, n_off = (tid >> 7) * 64;
    const int gid = lane >> 2, tig = lane & 3;
    float* Tb = TX + (size_t)b * NT * NL;
    #pragma unroll
    for (int mt = 0; mt < 2; mt++) {
        const int r0 = m0 + m_off + mt * 16 + gid;
        #pragma unroll
        for (int nt = 0; nt < 8; nt++) {
            const int col = n0 + n_off + nt * 8 + tig * 2;
            *(float2*)(Tb + (size_t)r0 * NL + col) =
                make_float2(acc[mt][nt][0], acc[mt][nt][1]);
            *(float2*)(Tb + (size_t)(r0 + 8) * NL + col) =
                make_float2(acc[mt][nt][2], acc[mt][nt][3]);
        }
    }
}

// Out: Out[b,o,t] = sum_l OW[o,l] * H[b,t,l] + ob[o] + in2[b,o,t]. 1x.
// A=OW mode0 (M=o), B=H mode0 (N=t). Grid (NT/128, ND/128, NB)
__global__ __launch_bounds__(256, 2)
void k_out_tc(const float* __restrict__ OW, const float* __restrict__ H,
              const float* __restrict__ ob, const float* __restrict__ in2,
              float* __restrict__ Out)
{
    const int b  = blockIdx.z;
    const int n0 = blockIdx.x * 128;   // t
    const int m0 = blockIdx.y * 128;   // o
    const float* Hb = H + (size_t)b * NT * NL;

    float acc[2][8][4];
    auto stage = [&](int kc, uint32_t bA, uint32_t bB) {
        stage_m0(bA, OW + (size_t)m0 * NL + kc * 32, NL);
        stage_m0(bB, Hb + (size_t)n0 * NL + kc * 32, NL);
    };
    gemm_run<0, 0, false>(NL / 32, stage, acc);

    const int tid = threadIdx.x, lane = tid & 31;
    const int m_off = ((tid >> 5) & 3) * 32, n_off = (tid >> 7) * 64;
    const int gid = lane >> 2, tig = lane & 3;
    #pragma unroll
    for (int mt = 0; mt < 2; mt++) {
        const int r0 = m0 + m_off + mt * 16 + gid;
        const float bi0 = ob[r0], bi1 = ob[r0 + 8];
        const size_t base0 = ((size_t)b * ND + r0) * NT;
        const size_t base1 = ((size_t)b * ND + r0 + 8) * NT;
        #pragma unroll
        for (int nt = 0; nt < 8; nt++) {
            const int col = n0 + n_off + nt * 8 + tig * 2;
            float2 q0 = *(const float2*)(in2 + base0 + col);
            float2 q1 = *(const float2*)(in2 + base1 + col);
            *(float2*)(Out + base0 + col) =
                make_float2(acc[mt][nt][0] + bi0 + q0.x, acc[mt][nt][1] + bi0 + q0.y);
            *(float2*)(Out + base1 + col) =
                make_float2(acc[mt][nt][2] + bi1 + q1.x, acc[mt][nt][3] + bi1 + q1.y);
        }
    }
}

// ---------------------------------------------------------------------------
// Elementwise / reductions
// ---------------------------------------------------------------------------
__device__ __forceinline__ float warpMax(float v) {
    #pragma unroll
    for (int o = 16; o > 0; o >>= 1) v = fmaxf(v, __shfl_xor_sync(0xffffffffu, v, o));
    return v;
}
__device__ __forceinline__ float warpSum(float v) {
    #pragma unroll
    for (int o = 16; o > 0; o >>= 1) v += __shfl_xor_sync(0xffffffffu, v, o);
    return v;
}

__global__ __launch_bounds__(256) void k_softmax(float* __restrict__ S)
{
    float* p = S + (size_t)blockIdx.x * NT;
    const int tid = threadIdx.x;
    float4 v0 = ((float4*)p)[tid];
    float4 v1 = ((float4*)p)[tid + 256];

    __shared__ float sm[8];
    float m = fmaxf(fmaxf(fmaxf(v0.x, v0.y), fmaxf(v0.z, v0.w)),
                    fmaxf(fmaxf(v1.x, v1.y), fmaxf(v1.z, v1.w)));
    m = warpMax(m);
    if ((tid & 31) == 0) sm[tid >> 5] = m;
    __syncthreads();
    if (tid < 32) {
        float t = (tid < 8) ? sm[tid] : -1e30f;
        t = warpMax(t);
        if (tid == 0) sm[0] = t;
    }
    __syncthreads();
    const float bm = sm[0];
    __syncthreads();

    v0.x = __expf(v0.x - bm); v0.y = __expf(v0.y - bm);
    v0.z = __expf(v0.z - bm); v0.w = __expf(v0.w - bm);
    v1.x = __expf(v1.x - bm); v1.y = __expf(v1.y - bm);
    v1.z = __expf(v1.z - bm); v1.w = __expf(v1.w - bm);
    float s = v0.x + v0.y + v0.z + v0.w + v1.x + v1.y + v1.z + v1.w;
    s = warpSum(s);
    if ((tid & 31) == 0) sm[tid >> 5] = s;
    __syncthreads();
    if (tid < 32) {
        float t = (tid < 8) ? sm[tid] : 0.f;
        t = warpSum(t);
        if (tid == 0) sm[0] = t;
    }
    __syncthreads();
    const float inv = 1.f / sm[0];
    v0.x *= inv; v0.y *= inv; v0.z *= inv; v0.w *= inv;
    v1.x *= inv; v1.y *= inv; v1.z *= inv; v1.w *= inv;
    ((float4*)p)[tid] = v0;
    ((float4*)p)[tid + 256] = v1;
}

__global__ __launch_bounds__(256) void k_stats(const float* __restrict__ TX)
{
    const int b = blockIdx.x >> 6;
    const int chunk = blockIdx.x & 63;
    const int tid = threadIdx.x;
    const float4* p4 = (const float4*)(TX + (size_t)b * NL * NT
                                          + (size_t)chunk * (NL * NT / 64));
    float s = 0.f, q = 0.f;
    #pragma unroll 4
    for (int i = tid; i < 4096; i += 256) {
        float4 v = p4[i];
        s += v.x + v.y + v.z + v.w;
        q += v.x * v.x + v.y * v.y + v.z * v.z + v.w * v.w;
    }
    __shared__ float rs[8], rq[8];
    s = warpSum(s); q = warpSum(q);
    if ((tid & 31) == 0) { rs[tid >> 5] = s; rq[tid >> 5] = q; }
    __syncthreads();
    if (tid < 32) {
        float t  = (tid < 8) ? rs[tid] : 0.f;
        float t2 = (tid < 8) ? rq[tid] : 0.f;
        t = warpSum(t); t2 = warpSum(t2);
        if (tid == 0) {
            g_part[blockIdx.x * 2]     = t;
            g_part[blockIdx.x * 2 + 1] = t2;
        }
    }
}

__global__ void k_finalize()
{
    const int b = threadIdx.x;
    if (b >= NB) return;
    float s = 0.f, q = 0.f;
    for (int c = 0; c < 64; c++) {
        s += g_part[(b * 64 + c) * 2];
        q += g_part[(b * 64 + c) * 2 + 1];
    }
    const float n = (float)NL * (float)NT;
    const float mean = s / n;
    const float var  = q / n - mean * mean;
    g_stats[2 * b]     = mean;
    g_stats[2 * b + 1] = rsqrtf(var + 1e-5f);
}

// gamma/beta transpose: src [NL, NT] -> dst [NT, NL]
__global__ void k_transpose(const float* __restrict__ src, float* __restrict__ dst)
{
    __shared__ float tile[32][33];
    const int x  = blockIdx.x * 32 + threadIdx.x;   // NT index
    const int y0 = blockIdx.y * 32;
    #pragma unroll
    for (int j = threadIdx.y; j < 32; j += 8)
        tile[j][threadIdx.x] = src[(size_t)(y0 + j) * NT + x];
    __syncthreads();
    const int xo  = blockIdx.y * 32 + threadIdx.x;  // NL index
    const int yo0 = blockIdx.x * 32;
    #pragma unroll
    for (int j = threadIdx.y; j < 32; j += 8)
        dst[(size_t)(yo0 + j) * NL + xo] = tile[threadIdx.x][j];
}

// H = relu((TX - mu) * rstd * G2 + B2), all [b,t,l]
__global__ __launch_bounds__(256) void k_ln(const float* __restrict__ TX,
                                            const float* __restrict__ G2,
                                            const float* __restrict__ B2,
                                            float* __restrict__ H)
{
    const int b = blockIdx.y;
    const size_t i = (size_t)blockIdx.x * 256 + threadIdx.x;
    const float mu = g_stats[2 * b], rs = g_stats[2 * b + 1];
    float4 x  = ((const float4*)(TX + (size_t)b * NL * NT))[i];
    float4 g  = ((const float4*)G2)[i];
    float4 be = ((const float4*)B2)[i];
    float4 h;
    h.x = fmaxf((x.x - mu) * rs * g.x + be.x, 0.f);
    h.y = fmaxf((x.y - mu) * rs * g.y + be.y, 0.f);
    h.z = fmaxf((x.z - mu) * rs * g.z + be.z, 0.f);
    h.w = fmaxf((x.w - mu) * rs * g.w + be.w, 0.f);
    ((float4*)(H + (size_t)b * NL * NT))[i] = h;
}

// ---------------------------------------------------------------------------
// Launch
// ---------------------------------------------------------------------------
extern "C" void kernel_launch(void* const* d_in, const int* in_sizes, int n_in,
                              void* d_out, int out_size)
{
    const float* input1  = (const float*)d_in[0];
    const float* input2  = (const float*)d_in[1];
    const float* theta_w = (const float*)d_in[2];
    const float* theta_b = (const float*)d_in[3];
    const float* phi_w   = (const float*)d_in[4];
    const float* phi_b   = (const float*)d_in[5];
    const float* g_w     = (const float*)d_in[6];
    const float* g_b     = (const float*)d_in[7];
    const float* ln_g    = (const float*)d_in[8];
    const float* ln_b    = (const float*)d_in[9];
    const float* out_w   = (const float*)d_in[10];
    const float* out_b   = (const float*)d_in[11];
    float* out = (float*)d_out;

    float *TH, *PH, *GX, *TX, *H, *S, *G2, *B2;
    cudaGetSymbolAddress((void**)&TH, g_TH);
    cudaGetSymbolAddress((void**)&PH, g_PH);
    cudaGetSymbolAddress((void**)&GX, g_GX);
    cudaGetSymbolAddress((void**)&TX, g_TX);
    cudaGetSymbolAddress((void**)&H,  g_H);
    cudaGetSymbolAddress((void**)&S,  g_S);
    cudaGetSymbolAddress((void**)&G2, g_G2);
    cudaGetSymbolAddress((void**)&B2, g_B2);

    cudaFuncSetAttribute(k_proj_tc<true>,  cudaFuncAttributeMaxDynamicSharedMemorySize, SMEMB);
    cudaFuncSetAttribute(k_proj_tc<false>, cudaFuncAttributeMaxDynamicSharedMemorySize, SMEMB);
    cudaFuncSetAttribute(k_scores_tc, cudaFuncAttributeMaxDynamicSharedMemorySize, SMEMB);
    cudaFuncSetAttribute(k_tx_tc,     cudaFuncAttributeMaxDynamicSharedMemorySize, SMEMB);
    cudaFuncSetAttribute(k_out_tc,    cudaFuncAttributeMaxDynamicSharedMemorySize, SMEMB);

    dim3 blk(256);

    dim3 gtr(NT / 32, NL / 32);
    k_transpose<<<gtr, dim3(32, 8)>>>(ln_g, G2);
    k_transpose<<<gtr, dim3(32, 8)>>>(ln_b, B2);

    dim3 gproj(NL / 128, NT / 128, NB);
    k_proj_tc<true ><<<gproj, blk, SMEMB>>>(theta_w, input2, theta_b, TH);
    k_proj_tc<true ><<<gproj, blk, SMEMB>>>(phi_w,   input1, phi_b,   PH);
    k_proj_tc<false><<<gproj, blk, SMEMB>>>(g_w,     input1, g_b,     GX);

    dim3 gsc(NT / 128, NT / 128, NB);
    k_scores_tc<<<gsc, blk, SMEMB>>>(TH, PH, S);

    k_softmax<<<NB * NT, 256>>>(S);

    dim3 gtx(NL / 128, NT / 128, NB);
    k_tx_tc<<<gtx, blk, SMEMB>>>(S, GX, TX);

    k_stats<<<NB * 64, 256>>>(TX);
    k_finalize<<<1, NB>>>();

    k_ln<<<dim3(NL * NT / 1024, NB), 256>>>(TX, G2, B2, H);

    dim3 gout(NT / 128, ND / 128, NB);
    k_out_tc<<<gout, blk, SMEMB>>>(out_w, H, out_b, input2, out);
}

// round 6
// speedup vs baseline: 2.8876x; 1.3561x over previous
#include <cuda_runtime.h>
#include <math.h>
#include <stdint.h>

#define NB 16
#define ND 1024
#define NL 512
#define NT 2048

// ---------------------------------------------------------------------------
// Scratch
// ---------------------------------------------------------------------------
__device__ float g_TH[(size_t)NB * NT * NL];   // theta proj [b,t,l]
__device__ float g_PH[(size_t)NB * NT * NL];   // phi proj   [b,s,l]
__device__ float g_GX[(size_t)NB * NT * NL];   // g proj     [b,s,l]
__device__ float g_TX[(size_t)NB * NT * NL];   // t_x        [b,t,l]
__device__ float g_H [(size_t)NB * NT * NL];   // LN+ReLU    [b,t,l]
__device__ float g_S [(size_t)NB * NT * NT];   // scores/p   [b,t,s]
__device__ float g_G2[(size_t)NT * NL];        // gamma^T [t,l]
__device__ float g_B2[(size_t)NT * NL];        // beta^T  [t,l]
__device__ float g_part[NB * 64 * 2];
__device__ float g_stats[NB * 2];

// Stage buffer geometry: tile A + tile B per stage, 3 stages.
static constexpr int TILE_B_OFF = 18432;
static constexpr int STAGE_BYTES = 36864;
static constexpr int SMEMB = 3 * STAGE_BYTES;   // 110592

// ---------------------------------------------------------------------------
// PTX helpers
// ---------------------------------------------------------------------------
__device__ __forceinline__ uint32_t f2tf(float f) {
    uint32_t r;
    asm("cvt.rna.tf32.f32 %0, %1;" : "=r"(r) : "f"(f));
    return r;
}

// tf32 m16n8k8
__device__ __forceinline__ void mma8(float* c, const uint32_t* a, const uint32_t* b) {
    asm volatile(
        "mma.sync.aligned.m16n8k8.row.col.f32.tf32.tf32.f32 "
        "{%0,%1,%2,%3}, {%4,%5,%6,%7}, {%8,%9}, {%0,%1,%2,%3};"
        : "+f"(c[0]), "+f"(c[1]), "+f"(c[2]), "+f"(c[3])
        : "r"(a[0]), "r"(a[1]), "r"(a[2]), "r"(a[3]), "r"(b[0]), "r"(b[1]));
}

// bf16 m16n8k16
__device__ __forceinline__ void mma16(float* c, const uint32_t* a, const uint32_t* b) {
    asm volatile(
        "mma.sync.aligned.m16n8k16.row.col.f32.bf16.bf16.f32 "
        "{%0,%1,%2,%3}, {%4,%5,%6,%7}, {%8,%9}, {%0,%1,%2,%3};"
        : "+f"(c[0]), "+f"(c[1]), "+f"(c[2]), "+f"(c[3])
        : "r"(a[0]), "r"(a[1]), "r"(a[2]), "r"(a[3]), "r"(b[0]), "r"(b[1]));
}

// Split (f0, f1) into packed bf16x2 hi + lo parts; f0 in low half.
__device__ __forceinline__ void bfsplit2(float f0, float f1, uint32_t& hi, uint32_t& lo) {
    asm("cvt.rn.bf16x2.f32 %0, %1, %2;" : "=r"(hi) : "f"(f1), "f"(f0));
    float h0 = __uint_as_float(hi << 16);
    float h1 = __uint_as_float(hi & 0xffff0000u);
    float l0 = f0 - h0, l1 = f1 - h1;
    asm("cvt.rn.bf16x2.f32 %0, %1, %2;" : "=r"(lo) : "f"(l1), "f"(l0));
}

__device__ __forceinline__ void cp16(uint32_t d, const float* s) {
    asm volatile("cp.async.cg.shared.global [%0], [%1], 16;" :: "r"(d), "l"(s));
}
__device__ __forceinline__ void cp_commit() {
    asm volatile("cp.async.commit_group;");
}
__device__ __forceinline__ void cp_wait2() {
    asm volatile("cp.async.wait_group 2;");
}

// Staging (256 threads, 16B chunks), natural gmem orientation.
// mode0: 128 rows x 32 floats -> smem rows padded to 144 B
__device__ __forceinline__ void stage_m0(uint32_t dst, const float* src, int stride) {
    const int tid = threadIdx.x;
    #pragma unroll
    for (int i = 0; i < 4; i++) {
        int id = tid + i * 256;
        int r = id >> 3, c = id & 7;
        cp16(dst + r * 144 + c * 16, src + (size_t)r * stride + c * 4);
    }
}
// mode1: 32 rows x 128 floats -> smem rows padded to 528 B
__device__ __forceinline__ void stage_m1(uint32_t dst, const float* src, int stride) {
    const int tid = threadIdx.x;
    #pragma unroll
    for (int i = 0; i < 4; i++) {
        int id = tid + i * 256;
        int r = id >> 5, c = id & 31;
        cp16(dst + r * 528 + c * 16, src + (size_t)r * stride + c * 4);
    }
}

// ---------------------------------------------------------------------------
// Pipelined GEMM core: 128x128 block, 8 warps (warp tile 32m x 64n),
// K chunks of 32. AM/BM select operand orientation.
// PREC: 0 = 1x tf32 (m16n8k8), 1 = bf16x3 (m16n8k16, hi/lo split, 3 mmas).
//   A element (r,k):  AM0: sA[r*36+k]   AM1: sA[k*132+r]
//   B element (k,n):  BM0: sB[n*36+k]   BM1: sB[k*132+n]
// ---------------------------------------------------------------------------
template<int AM, int BM, int PREC, class StageF>
__device__ __forceinline__ void gemm_run(int KC, StageF stage, float (*acc)[8][4])
{
    extern __shared__ char dsm[];
    const uint32_t sb = (uint32_t)__cvta_generic_to_shared(dsm);
    const int tid  = threadIdx.x;
    const int lane = tid & 31;
    const int m_off = ((tid >> 5) & 3) * 32;
    const int n_off = (tid >> 7) * 64;
    const int gid = lane >> 2, tig = lane & 3;

    #pragma unroll
    for (int i = 0; i < 2; i++)
        #pragma unroll
        for (int j = 0; j < 8; j++)
            #pragma unroll
            for (int k = 0; k < 4; k++) acc[i][j][k] = 0.f;

    #pragma unroll
    for (int p = 0; p < 3; p++) {
        if (p < KC) stage(p, sb + p * STAGE_BYTES, sb + p * STAGE_BYTES + TILE_B_OFF);
        cp_commit();
    }

    for (int kc = 0; kc < KC; kc++) {
        const int s = kc % 3;
        const float* sA = (const float*)(dsm + s * STAGE_BYTES);
        const float* sB = (const float*)(dsm + s * STAGE_BYTES + TILE_B_OFF);
        cp_wait2();
        __syncthreads();

        if (PREC == 1) {
            // ---- bf16x3: two K=16 sub-chunks ----
            #pragma unroll
            for (int kh = 0; kh < 2; kh++) {
                const int k0 = kh * 16 + 2 * tig;
                uint32_t ah[2][4], al[2][4];
                #pragma unroll
                for (int mt = 0; mt < 2; mt++) {
                    const int r0 = m_off + mt * 16 + gid;
                    float f[8];
                    if (AM == 0) {
                        float2 v;
                        v = *(const float2*)(sA + r0 * 36 + k0);           f[0]=v.x; f[1]=v.y;
                        v = *(const float2*)(sA + (r0 + 8) * 36 + k0);     f[2]=v.x; f[3]=v.y;
                        v = *(const float2*)(sA + r0 * 36 + k0 + 8);       f[4]=v.x; f[5]=v.y;
                        v = *(const float2*)(sA + (r0 + 8) * 36 + k0 + 8); f[6]=v.x; f[7]=v.y;
                    } else {
                        f[0] = sA[k0 * 132 + r0];           f[1] = sA[(k0 + 1) * 132 + r0];
                        f[2] = sA[k0 * 132 + r0 + 8];       f[3] = sA[(k0 + 1) * 132 + r0 + 8];
                        f[4] = sA[(k0 + 8) * 132 + r0];     f[5] = sA[(k0 + 9) * 132 + r0];
                        f[6] = sA[(k0 + 8) * 132 + r0 + 8]; f[7] = sA[(k0 + 9) * 132 + r0 + 8];
                    }
                    bfsplit2(f[0], f[1], ah[mt][0], al[mt][0]);
                    bfsplit2(f[2], f[3], ah[mt][1], al[mt][1]);
                    bfsplit2(f[4], f[5], ah[mt][2], al[mt][2]);
                    bfsplit2(f[6], f[7], ah[mt][3], al[mt][3]);
                }
                #pragma unroll
                for (int nt = 0; nt < 8; nt++) {
                    const int n = n_off + nt * 8 + gid;
                    float g0, g1, g2, g3;
                    if (BM == 0) {
                        float2 v0 = *(const float2*)(sB + n * 36 + k0);
                        float2 v1 = *(const float2*)(sB + n * 36 + k0 + 8);
                        g0 = v0.x; g1 = v0.y; g2 = v1.x; g3 = v1.y;
                    } else {
                        g0 = sB[k0 * 132 + n];       g1 = sB[(k0 + 1) * 132 + n];
                        g2 = sB[(k0 + 8) * 132 + n]; g3 = sB[(k0 + 9) * 132 + n];
                    }
                    uint32_t bh[2], bl[2];
                    bfsplit2(g0, g1, bh[0], bl[0]);
                    bfsplit2(g2, g3, bh[1], bl[1]);
                    #pragma unroll
                    for (int mt = 0; mt < 2; mt++) {
                        mma16(acc[mt][nt], al[mt], bh);
                        mma16(acc[mt][nt], ah[mt], bl);
                        mma16(acc[mt][nt], ah[mt], bh);
                    }
                }
            }
        } else {
            // ---- 1x tf32: four K=8 sub-chunks ----
            #pragma unroll
            for (int k8 = 0; k8 < 4; k8++) {
                const int kb = k8 * 8;
                uint32_t a[2][4];
                #pragma unroll
                for (int mt = 0; mt < 2; mt++) {
                    const int r0 = m_off + mt * 16 + gid;
                    if (AM == 0) {
                        a[mt][0] = f2tf(sA[r0 * 36 + kb + tig]);
                        a[mt][1] = f2tf(sA[(r0 + 8) * 36 + kb + tig]);
                        a[mt][2] = f2tf(sA[r0 * 36 + kb + tig + 4]);
                        a[mt][3] = f2tf(sA[(r0 + 8) * 36 + kb + tig + 4]);
                    } else {
                        a[mt][0] = f2tf(sA[(kb + tig) * 132 + r0]);
                        a[mt][1] = f2tf(sA[(kb + tig) * 132 + r0 + 8]);
                        a[mt][2] = f2tf(sA[(kb + tig + 4) * 132 + r0]);
                        a[mt][3] = f2tf(sA[(kb + tig + 4) * 132 + r0 + 8]);
                    }
                }
                #pragma unroll
                for (int nt = 0; nt < 8; nt++) {
                    const int n = n_off + nt * 8 + gid;
                    uint32_t bb[2];
                    if (BM == 0) {
                        bb[0] = f2tf(sB[n * 36 + kb + tig]);
                        bb[1] = f2tf(sB[n * 36 + kb + tig + 4]);
                    } else {
                        bb[0] = f2tf(sB[(kb + tig) * 132 + n]);
                        bb[1] = f2tf(sB[(kb + tig + 4) * 132 + n]);
                    }
                    #pragma unroll
                    for (int mt = 0; mt < 2; mt++)
                        mma8(acc[mt][nt], a[mt], bb);
                }
            }
        }
        __syncthreads();
        if (kc + 3 < KC)
            stage(kc + 3, sb + s * STAGE_BYTES, sb + s * STAGE_BYTES + TILE_B_OFF);
        cp_commit();
    }
}

// ---------------------------------------------------------------------------
// GEMM kernels
// ---------------------------------------------------------------------------

// Projection: C[b,t,l] = sum_d X[b,d,t] * W[l,d] + bias[l]
// A = X (M=t, mode1), B = W (N=l, mode0). Grid: (NL/128, NT/128, NB)
template<int PREC>
__global__ __launch_bounds__(256, 2)
void k_proj_tc(const float* __restrict__ W, const float* __restrict__ X,
               const float* __restrict__ bias, float* __restrict__ C)
{
    const int b  = blockIdx.z;
    const int n0 = blockIdx.x * 128;   // l
    const int m0 = blockIdx.y * 128;   // t
    const float* Xb = X + (size_t)b * ND * NT;

    float acc[2][8][4];
    auto stage = [&](int kc, uint32_t bA, uint32_t bB) {
        stage_m1(bA, Xb + (size_t)(kc * 32) * NT + m0, NT);
        stage_m0(bB, W  + (size_t)n0 * ND + kc * 32, ND);
    };
    gemm_run<1, 0, PREC>(ND / 32, stage, acc);

    const int tid = threadIdx.x, lane = tid & 31;
    const int m_off = ((tid >> 5) & 3) * 32, n_off = (tid >> 7) * 64;
    const int gid = lane >> 2, tig = lane & 3;
    float* Cb = C + (size_t)b * NT * NL;
    #pragma unroll
    for (int mt = 0; mt < 2; mt++) {
        const int r0 = m0 + m_off + mt * 16 + gid;
        #pragma unroll
        for (int nt = 0; nt < 8; nt++) {
            const int col = n0 + n_off + nt * 8 + tig * 2;
            float2 bi = *(const float2*)(bias + col);
            *(float2*)(Cb + (size_t)r0 * NL + col) =
                make_float2(acc[mt][nt][0] + bi.x, acc[mt][nt][1] + bi.y);
            *(float2*)(Cb + (size_t)(r0 + 8) * NL + col) =
                make_float2(acc[mt][nt][2] + bi.x, acc[mt][nt][3] + bi.y);
        }
    }
}

// Scores: S[b,t,s] = sum_l TH[b,t,l] * PH[b,s,l]. A/B mode0. bf16x3. Grid (16,16,NB)
__global__ __launch_bounds__(256, 2)
void k_scores_tc(const float* __restrict__ TH, const float* __restrict__ PH,
                 float* __restrict__ S)
{
    const int b  = blockIdx.z;
    const int n0 = blockIdx.x * 128;   // s
    const int m0 = blockIdx.y * 128;   // t
    const float* A  = TH + (size_t)b * NT * NL;
    const float* Bp = PH + (size_t)b * NT * NL;

    float acc[2][8][4];
    auto stage = [&](int kc, uint32_t bA, uint32_t bB) {
        stage_m0(bA, A  + (size_t)m0 * NL + kc * 32, NL);
        stage_m0(bB, Bp + (size_t)n0 * NL + kc * 32, NL);
    };
    gemm_run<0, 0, 1>(NL / 32, stage, acc);

    const int tid = threadIdx.x, lane = tid & 31;
    const int m_off = ((tid >> 5) & 3) * 32, n_off = (tid >> 7) * 64;
    const int gid = lane >> 2, tig = lane & 3;
    float* Sb = S + (size_t)b * NT * NT;
    #pragma unroll
    for (int mt = 0; mt < 2; mt++) {
        const int r0 = m0 + m_off + mt * 16 + gid;
        #pragma unroll
        for (int nt = 0; nt < 8; nt++) {
            const int col = n0 + n_off + nt * 8 + tig * 2;
            *(float2*)(Sb + (size_t)r0 * NT + col) =
                make_float2(acc[mt][nt][0], acc[mt][nt][1]);
            *(float2*)(Sb + (size_t)(r0 + 8) * NT + col) =
                make_float2(acc[mt][nt][2], acc[mt][nt][3]);
        }
    }
}

// t_x: TX[b,t,l] = sum_s P[b,t,s] * GX[b,s,l]. A=P mode0, B=GX mode1. tf32 1x.
// Grid (NL/128, NT/128, NB)
__global__ __launch_bounds__(256, 2)
void k_tx_tc(const float* __restrict__ P, const float* __restrict__ GX,
             float* __restrict__ TX)
{
    const int b  = blockIdx.z;
    const int n0 = blockIdx.x * 128;   // l
    const int m0 = blockIdx.y * 128;   // t
    const float* A  = P  + (size_t)b * NT * NT;
    const float* Bp = GX + (size_t)b * NT * NL;

    float acc[2][8][4];
    auto stage = [&](int kc, uint32_t bA, uint32_t bB) {
        stage_m0(bA, A  + (size_t)m0 * NT + kc * 32, NT);
        stage_m1(bB, Bp + (size_t)(kc * 32) * NL + n0, NL);
    };
    gemm_run<0, 1, 0>(NT / 32, stage, acc);

    const int tid = threadIdx.x, lane = tid & 31;
    const int m_off = ((tid >> 5) & 3) * 32, n_off = (tid >> 7) * 64;
    const int gid = lane >> 2, tig = lane & 3;
    float* Tb = TX + (size_t)b * NT * NL;
    #pragma unroll
    for (int mt = 0; mt < 2; mt++) {
        const int r0 = m0 + m_off + mt * 16 + gid;
        #pragma unroll
        for (int nt = 0; nt < 8; nt++) {
            const int col = n0 + n_off + nt * 8 + tig * 2;
            *(float2*)(Tb + (size_t)r0 * NL + col) =
                make_float2(acc[mt][nt][0], acc[mt][nt][1]);
            *(float2*)(Tb + (size_t)(r0 + 8) * NL + col) =
                make_float2(acc[mt][nt][2], acc[mt][nt][3]);
        }
    }
}

// Out: Out[b,o,t] = sum_l OW[o,l] * H[b,t,l] + ob[o] + in2[b,o,t]. tf32 1x.
// A=OW mode0 (M=o), B=H mode0 (N=t). Grid (NT/128, ND/128, NB)
__global__ __launch_bounds__(256, 2)
void k_out_tc(const float* __restrict__ OW, const float* __restrict__ H,
              const float* __restrict__ ob, const float* __restrict__ in2,
              float* __restrict__ Out)
{
    const int b  = blockIdx.z;
    const int n0 = blockIdx.x * 128;   // t
    const int m0 = blockIdx.y * 128;   // o
    const float* Hb = H + (size_t)b * NT * NL;

    float acc[2][8][4];
    auto stage = [&](int kc, uint32_t bA, uint32_t bB) {
        stage_m0(bA, OW + (size_t)m0 * NL + kc * 32, NL);
        stage_m0(bB, Hb + (size_t)n0 * NL + kc * 32, NL);
    };
    gemm_run<0, 0, 0>(NL / 32, stage, acc);

    const int tid = threadIdx.x, lane = tid & 31;
    const int m_off = ((tid >> 5) & 3) * 32, n_off = (tid >> 7) * 64;
    const int gid = lane >> 2, tig = lane & 3;
    #pragma unroll
    for (int mt = 0; mt < 2; mt++) {
        const int r0 = m0 + m_off + mt * 16 + gid;
        const float bi0 = ob[r0], bi1 = ob[r0 + 8];
        const size_t base0 = ((size_t)b * ND + r0) * NT;
        const size_t base1 = ((size_t)b * ND + r0 + 8) * NT;
        #pragma unroll
        for (int nt = 0; nt < 8; nt++) {
            const int col = n0 + n_off + nt * 8 + tig * 2;
            float2 q0 = *(const float2*)(in2 + base0 + col);
            float2 q1 = *(const float2*)(in2 + base1 + col);
            *(float2*)(Out + base0 + col) =
                make_float2(acc[mt][nt][0] + bi0 + q0.x, acc[mt][nt][1] + bi0 + q0.y);
            *(float2*)(Out + base1 + col) =
                make_float2(acc[mt][nt][2] + bi1 + q1.x, acc[mt][nt][3] + bi1 + q1.y);
        }
    }
}

// ---------------------------------------------------------------------------
// Elementwise / reductions
// ---------------------------------------------------------------------------
__device__ __forceinline__ float warpMax(float v) {
    #pragma unroll
    for (int o = 16; o > 0; o >>= 1) v = fmaxf(v, __shfl_xor_sync(0xffffffffu, v, o));
    return v;
}
__device__ __forceinline__ float warpSum(float v) {
    #pragma unroll
    for (int o = 16; o > 0; o >>= 1) v += __shfl_xor_sync(0xffffffffu, v, o);
    return v;
}

__global__ __launch_bounds__(256) void k_softmax(float* __restrict__ S)
{
    float* p = S + (size_t)blockIdx.x * NT;
    const int tid = threadIdx.x;
    float4 v0 = ((float4*)p)[tid];
    float4 v1 = ((float4*)p)[tid + 256];

    __shared__ float sm[8];
    float m = fmaxf(fmaxf(fmaxf(v0.x, v0.y), fmaxf(v0.z, v0.w)),
                    fmaxf(fmaxf(v1.x, v1.y), fmaxf(v1.z, v1.w)));
    m = warpMax(m);
    if ((tid & 31) == 0) sm[tid >> 5] = m;
    __syncthreads();
    if (tid < 32) {
        float t = (tid < 8) ? sm[tid] : -1e30f;
        t = warpMax(t);
        if (tid == 0) sm[0] = t;
    }
    __syncthreads();
    const float bm = sm[0];
    __syncthreads();

    v0.x = __expf(v0.x - bm); v0.y = __expf(v0.y - bm);
    v0.z = __expf(v0.z - bm); v0.w = __expf(v0.w - bm);
    v1.x = __expf(v1.x - bm); v1.y = __expf(v1.y - bm);
    v1.z = __expf(v1.z - bm); v1.w = __expf(v1.w - bm);
    float s = v0.x + v0.y + v0.z + v0.w + v1.x + v1.y + v1.z + v1.w;
    s = warpSum(s);
    if ((tid & 31) == 0) sm[tid >> 5] = s;
    __syncthreads();
    if (tid < 32) {
        float t = (tid < 8) ? sm[tid] : 0.f;
        t = warpSum(t);
        if (tid == 0) sm[0] = t;
    }
    __syncthreads();
    const float inv = 1.f / sm[0];
    v0.x *= inv; v0.y *= inv; v0.z *= inv; v0.w *= inv;
    v1.x *= inv; v1.y *= inv; v1.z *= inv; v1.w *= inv;
    ((float4*)p)[tid] = v0;
    ((float4*)p)[tid + 256] = v1;
}

__global__ __launch_bounds__(256) void k_stats(const float* __restrict__ TX)
{
    const int b = blockIdx.x >> 6;
    const int chunk = blockIdx.x & 63;
    const int tid = threadIdx.x;
    const float4* p4 = (const float4*)(TX + (size_t)b * NL * NT
                                          + (size_t)chunk * (NL * NT / 64));
    float s = 0.f, q = 0.f;
    #pragma unroll 4
    for (int i = tid; i < 4096; i += 256) {
        float4 v = p4[i];
        s += v.x + v.y + v.z + v.w;
        q += v.x * v.x + v.y * v.y + v.z * v.z + v.w * v.w;
    }
    __shared__ float rs[8], rq[8];
    s = warpSum(s); q = warpSum(q);
    if ((tid & 31) == 0) { rs[tid >> 5] = s; rq[tid >> 5] = q; }
    __syncthreads();
    if (tid < 32) {
        float t  = (tid < 8) ? rs[tid] : 0.f;
        float t2 = (tid < 8) ? rq[tid] : 0.f;
        t = warpSum(t); t2 = warpSum(t2);
        if (tid == 0) {
            g_part[blockIdx.x * 2]     = t;
            g_part[blockIdx.x * 2 + 1] = t2;
        }
    }
}

__global__ void k_finalize()
{
    const int b = threadIdx.x;
    if (b >= NB) return;
    float s = 0.f, q = 0.f;
    for (int c = 0; c < 64; c++) {
        s += g_part[(b * 64 + c) * 2];
        q += g_part[(b * 64 + c) * 2 + 1];
    }
    const float n = (float)NL * (float)NT;
    const float mean = s / n;
    const float var  = q / n - mean * mean;
    g_stats[2 * b]     = mean;
    g_stats[2 * b + 1] = rsqrtf(var + 1e-5f);
}

// gamma/beta transpose: src [NL, NT] -> dst [NT, NL]
__global__ void k_transpose(const float* __restrict__ src, float* __restrict__ dst)
{
    __shared__ float tile[32][33];
    const int x  = blockIdx.x * 32 + threadIdx.x;   // NT index
    const int y0 = blockIdx.y * 32;
    #pragma unroll
    for (int j = threadIdx.y; j < 32; j += 8)
        tile[j][threadIdx.x] = src[(size_t)(y0 + j) * NT + x];
    __syncthreads();
    const int xo  = blockIdx.y * 32 + threadIdx.x;  // NL index
    const int yo0 = blockIdx.x * 32;
    #pragma unroll
    for (int j = threadIdx.y; j < 32; j += 8)
        dst[(size_t)(yo0 + j) * NL + xo] = tile[threadIdx.x][j];
}

// H = relu((TX - mu) * rstd * G2 + B2), all [b,t,l]
__global__ __launch_bounds__(256) void k_ln(const float* __restrict__ TX,
                                            const float* __restrict__ G2,
                                            const float* __restrict__ B2,
                                            float* __restrict__ H)
{
    const int b = blockIdx.y;
    const size_t i = (size_t)blockIdx.x * 256 + threadIdx.x;
    const float mu = g_stats[2 * b], rs = g_stats[2 * b + 1];
    float4 x  = ((const float4*)(TX + (size_t)b * NL * NT))[i];
    float4 g  = ((const float4*)G2)[i];
    float4 be = ((const float4*)B2)[i];
    float4 h;
    h.x = fmaxf((x.x - mu) * rs * g.x + be.x, 0.f);
    h.y = fmaxf((x.y - mu) * rs * g.y + be.y, 0.f);
    h.z = fmaxf((x.z - mu) * rs * g.z + be.z, 0.f);
    h.w = fmaxf((x.w - mu) * rs * g.w + be.w, 0.f);
    ((float4*)(H + (size_t)b * NL * NT))[i] = h;
}

// ---------------------------------------------------------------------------
// Launch
// ---------------------------------------------------------------------------
extern "C" void kernel_launch(void* const* d_in, const int* in_sizes, int n_in,
                              void* d_out, int out_size)
{
    const float* input1  = (const float*)d_in[0];
    const float* input2  = (const float*)d_in[1];
    const float* theta_w = (const float*)d_in[2];
    const float* theta_b = (const float*)d_in[3];
    const float* phi_w   = (const float*)d_in[4];
    const float* phi_b   = (const float*)d_in[5];
    const float* g_w     = (const float*)d_in[6];
    const float* g_b     = (const float*)d_in[7];
    const float* ln_g    = (const float*)d_in[8];
    const float* ln_b    = (const float*)d_in[9];
    const float* out_w   = (const float*)d_in[10];
    const float* out_b   = (const float*)d_in[11];
    float* out = (float*)d_out;

    float *TH, *PH, *GX, *TX, *H, *S, *G2, *B2;
    cudaGetSymbolAddress((void**)&TH, g_TH);
    cudaGetSymbolAddress((void**)&PH, g_PH);
    cudaGetSymbolAddress((void**)&GX, g_GX);
    cudaGetSymbolAddress((void**)&TX, g_TX);
    cudaGetSymbolAddress((void**)&H,  g_H);
    cudaGetSymbolAddress((void**)&S,  g_S);
    cudaGetSymbolAddress((void**)&G2, g_G2);
    cudaGetSymbolAddress((void**)&B2, g_B2);

    cudaFuncSetAttribute(k_proj_tc<1>, cudaFuncAttributeMaxDynamicSharedMemorySize, SMEMB);
    cudaFuncSetAttribute(k_proj_tc<0>, cudaFuncAttributeMaxDynamicSharedMemorySize, SMEMB);
    cudaFuncSetAttribute(k_scores_tc,  cudaFuncAttributeMaxDynamicSharedMemorySize, SMEMB);
    cudaFuncSetAttribute(k_tx_tc,      cudaFuncAttributeMaxDynamicSharedMemorySize, SMEMB);
    cudaFuncSetAttribute(k_out_tc,     cudaFuncAttributeMaxDynamicSharedMemorySize, SMEMB);

    dim3 blk(256);

    dim3 gtr(NT / 32, NL / 32);
    k_transpose<<<gtr, dim3(32, 8)>>>(ln_g, G2);
    k_transpose<<<gtr, dim3(32, 8)>>>(ln_b, B2);

    dim3 gproj(NL / 128, NT / 128, NB);
    k_proj_tc<1><<<gproj, blk, SMEMB>>>(theta_w, input2, theta_b, TH);
    k_proj_tc<1><<<gproj, blk, SMEMB>>>(phi_w,   input1, phi_b,   PH);
    k_proj_tc<0><<<gproj, blk, SMEMB>>>(g_w,     input1, g_b,     GX);

    dim3 gsc(NT / 128, NT / 128, NB);
    k_scores_tc<<<gsc, blk, SMEMB>>>(TH, PH, S);

    k_softmax<<<NB * NT, 256>>>(S);

    dim3 gtx(NL / 128, NT / 128, NB);
    k_tx_tc<<<gtx, blk, SMEMB>>>(S, GX, TX);

    k_stats<<<NB * 64, 256>>>(TX);
    k_finalize<<<1, NB>>>();

    k_ln<<<dim3(NL * NT / 1024, NB), 256>>>(TX, G2, B2, H);

    dim3 gout(NT / 128, ND / 128, NB);
    k_out_tc<<<gout, blk, SMEMB>>>(out_w, H, out_b, input2, out);
}